// round 15
// baseline (speedup 1.0000x reference)
#include <cuda_runtime.h>
#include <cuda_fp16.h>
#include <cstdint>

// ---------------- problem constants ----------------
#define B_     4
#define S_     16
#define NF     64            // frames = B*S
#define H_     32
#define W_     32
#define HW_    1024
#define CL_    64            // LSTM channels per layer; gate channels = 256
#define NT     18            // N tiles per frame (64 padded pixels each)
#define PLST   1160          // halves per plane copy
#define NCPY   2             // copies per plane (shift 0 / shift 1)
#define BST    72            // B smem row stride in halves
#define HTS    66            // htile row stride (floats)

// ---------------- device scratch (static; no allocations) ----------------
// __device__ globals are zero-initialized at load; halo positions are never
// written by any kernel, so they stay zero (the conv's zero padding).
__device__ __align__(16) __half g_x7[(size_t)NF * 32 * NCPY * PLST + 64 + 2048];
__device__ __align__(16) __half g_h7[(size_t)NF * 64 * NCPY * PLST + 64 + 2048];
// fragment-ordered fp16 weights (lstm-channel-major row remap):
// [chunk][mtile(2)][warp(4)][mt(2)][ks(2)][lane(32)][4 u32]
__device__ __align__(16) uint32_t g_wf0[9  * 4096];
__device__ __align__(16) uint32_t g_wf1[18 * 4096];

// taps in order {-35,-34,-33,-1,0,1,33,34,35}:
// copy q = tap&1; effective (even) offset = tap - q.
__constant__ int c_q[9]   = { 1, 0, 1, 1, 0, 1, 1, 0, 1 };
__constant__ int c_off[9] = { -36, -34, -34, -2, 0, 0, 32, 34, 34 };

// ---------------- helpers ----------------
__device__ __forceinline__ float sigm(float x) { return 1.0f / (1.0f + __expf(-x)); }

__device__ __forceinline__ uint32_t smem_u32(const void* p) {
    uint32_t a;
    asm("{ .reg .u64 t; cvta.to.shared.u64 t, %1; cvt.u32.u64 %0, t; }" : "=r"(a) : "l"(p));
    return a;
}

__device__ __forceinline__ void cp4(uint32_t saddr, const void* gptr) {
    asm volatile("cp.async.ca.shared.global [%0], [%1], 4;"
                 :: "r"(saddr), "l"(gptr) : "memory");
}
__device__ __forceinline__ void cp_commit() {
    asm volatile("cp.async.commit_group;" ::: "memory");
}
__device__ __forceinline__ void cp_wait2() {
    asm volatile("cp.async.wait_group 2;" ::: "memory");
}

__device__ __forceinline__ void ldsm4t(uint32_t r[4], uint32_t addr) {
    asm volatile("ldmatrix.sync.aligned.m8n8.x4.trans.shared.b16 {%0,%1,%2,%3}, [%4];"
        : "=r"(r[0]), "=r"(r[1]), "=r"(r[2]), "=r"(r[3]) : "r"(addr));
}

__device__ __forceinline__ void mma16816(float d[4], uint32_t a0, uint32_t a1,
                                         uint32_t a2, uint32_t a3,
                                         uint32_t b0, uint32_t b1) {
    asm volatile(
        "mma.sync.aligned.m16n8k16.row.col.f32.f16.f16.f32 "
        "{%0,%1,%2,%3}, {%4,%5,%6,%7}, {%8,%9}, {%0,%1,%2,%3};"
        : "+f"(d[0]), "+f"(d[1]), "+f"(d[2]), "+f"(d[3])
        : "r"(a0), "r"(a1), "r"(a2), "r"(a3), "r"(b0), "r"(b1));
}

// ---------------- prologue kernels ----------------
// build the 2 shifted fp16 copies of padded x planes (interior positions only)
__global__ void k_fill_x7(const float* __restrict__ x) {
    __half* xb = g_x7 + 64;
    const int n = NF * 32 * HW_;
    for (int i = blockIdx.x * blockDim.x + threadIdx.x; i < n;
         i += gridDim.x * blockDim.x) {
        int plane = i >> 10, px = i & 1023;
        int r = px >> 5, c = px & 31;
        int p = (r + 1) * 34 + (c + 1);
        __half hv = __float2half_rn(x[i]);
        __half* base = xb + (size_t)plane * NCPY * PLST;
        base[p] = hv;               // copy0 (shift 0)
        base[PLST + p - 1] = hv;    // copy1 (shift 1)
    }
}

// pack weights into mma A-fragment order with lstm-channel-major row remap:
// warp-local row wr (0..31): gate = wr>>3, lstm_local = wr&7
// -> oc = gate*64 + mtile*32 + w*8 + lstm_local
// A frag slot (lane, reg r): wr = mt*16 + (lane>>2) + (r&1)*8,
//                            ci = ks*16 + (lane&3)*2 + (r>>1)*8 + {0,1}
__global__ void k_pack_wf(const float* __restrict__ w0, const float* __restrict__ w1) {
    const int n0 = 9 * 4096, n1 = 18 * 4096;
    for (int i = blockIdx.x * blockDim.x + threadIdx.x; i < n0 + n1;
         i += gridDim.x * blockDim.x) {
        bool l1sel = (i >= n0);
        int j = l1sel ? (i - n0) : i;
        int r     = j & 3;
        int lane  = (j >> 2) & 31;
        int ks    = (j >> 7) & 1;
        int mt    = (j >> 8) & 1;
        int w     = (j >> 9) & 3;
        int mtile = (j >> 11) & 1;
        int ch    = j >> 12;
        int gate  = mt * 2 + (r & 1);
        int oc    = gate * CL_ + mtile * 32 + w * 8 + (lane >> 2);
        int kbase = ks * 16 + (lane & 3) * 2 + (r >> 1) * 8;
        uint32_t outv = 0;
#pragma unroll
        for (int h = 0; h < 2; ++h) {
            int ci = kbase + h;    // 0..31
            float v = l1sel
                ? w1[((size_t)oc * 64 + (ch & 1) * 32 + ci) * 9 + (ch >> 1)]
                : w0[((size_t)oc * 32 + ci) * 9 + ch];
            outv |= (uint32_t)__half_as_ushort(__float2half_rn(v)) << (16 * h);
        }
        (l1sel ? g_wf1 : g_wf0)[j] = outv;
    }
}

// ---------------- fused GEMM + scan kernel ----------------
// Persistent CTA = 128 threads, owns (batch b, 64-pixel ntile, 32-channel
// mtile). Loops s=0..15: conv-GEMM (M=128 = 32 ch x 4 gates, N=64, K=9*CIN)
// with cp.async B pipeline running CONTINUOUSLY across frames, then in-register
// minLSTM scan update (cst[16] per thread persists across s), then coalesced
// masked h write via an smem tile. No gates scratch ever touches DRAM.
template <int CPT, bool LAST>   // CPT: chunks per tap (CIN=32*CPT)
__device__ __forceinline__ void fused_body(const __half* __restrict__ bpl,
                                           const uint32_t* __restrict__ wf,
                                           const float* __restrict__ bias,
                                           float* __restrict__ out)
{
    __shared__ __align__(16) __half sBt[4][32 * BST];   // 18.4 KB
    __shared__ __align__(16) float  htile[32 * HTS];    // 8.4 KB

    const int tid  = threadIdx.x, w = tid >> 5, lane = tid & 31;
    const int g4 = lane >> 2, t4 = lane & 3;
    const int ntile = blockIdx.x, mtile = blockIdx.y, b = blockIdx.z;
    const int p0 = ntile * 64;
    const int NCH = 9 * CPT;
    constexpr int CIN = CPT * 32;

    const int cis = tid >> 3, gs = tid & 7;   // B staging coords

    // this thread's lstm channel + its biases
    const int ell = mtile * 32 + w * 8 + g4;
    const float bi = __ldg(bias + ell);
    const float bf = __ldg(bias + 64 + ell);
    const float bo = __ldg(bias + 128 + ell);
    const float bc = __ldg(bias + 192 + ell);

    // async B chunk copy (8 x 4B per thread)
    auto copyB = [&](int s_, int ch_, int buf) {
        const int tap = (CPT == 1) ? ch_ : (ch_ >> 1);
        const int ci0 = (CPT == 1) ? 0 : ((ch_ & 1) * 32);
        const __half* bp = bpl
            + ((size_t)((b * S_ + s_) * CIN + ci0) * NCPY + c_q[tap]) * PLST
            + p0 + c_off[tap];
        uint32_t sa = smem_u32(sBt[buf]);
#pragma unroll
        for (int rr = 0; rr < 2; ++rr) {
            int r = cis + rr * 16;
            const __half* src = bp + (size_t)r * (NCPY * PLST) + gs * 8;
            uint32_t dst = sa + (uint32_t)(r * BST + gs * 8) * 2;
#pragma unroll
            for (int jj = 0; jj < 4; ++jj)
                cp4(dst + jj * 4, src + jj * 2);
        }
    };

    float d[2][8][4];
#pragma unroll
    for (int mt = 0; mt < 2; ++mt)
#pragma unroll
        for (int nt = 0; nt < 8; ++nt)
#pragma unroll
            for (int q = 0; q < 4; ++q) d[mt][nt][q] = 0.0f;

    float cst[16];
#pragma unroll
    for (int j = 0; j < 16; ++j) cst[j] = 0.5f;

    // ---- continuous pipeline prologue: chunks (0,0),(0,1) in flight ----
    copyB(0, 0, 0); cp_commit();
    copyB(0, 1, 1); cp_commit();
    int ps = 0, pch = 2;   // prefetch cursor = current + 2
    int cc = 0;            // global chunk counter

#pragma unroll 1
    for (int s = 0; s < S_; ++s) {
#pragma unroll 1
        for (int ch = 0; ch < NCH; ++ch) {
            // ---- prefetch chunk cc+2 (empty commit keeps group count) ----
            if (ps < S_) copyB(ps, pch, (cc + 2) & 3);
            cp_commit();
            if (++pch == NCH) { pch = 0; ++ps; }

            // ---- A fragments: 4 independent LDG.128 (L1/L2-resident) ----
            const uint4* af = (const uint4*)wf
                            + ((size_t)(ch * 2 + mtile) * 4 + w) * 128 + lane;
            uint4 afr[2][2];
#pragma unroll
            for (int mt = 0; mt < 2; ++mt)
#pragma unroll
                for (int ks = 0; ks < 2; ++ks)
                    afr[mt][ks] = af[(mt * 2 + ks) * 32];

            // ---- wait for chunk cc, make visible ----
            cp_wait2();
            __syncthreads();

            // ---- B fragments via ldmatrix.trans ----
            const uint32_t sBu = smem_u32(sBt[cc & 3]);
            uint32_t bfr[2][4][4];
#pragma unroll
            for (int kk = 0; kk < 2; ++kk)
#pragma unroll
                for (int np = 0; np < 4; ++np) {
                    int ci = kk * 16 + ((lane >> 3) & 1) * 8 + (lane & 7);
                    int px = np * 16 + (lane >> 4) * 8;
                    ldsm4t(bfr[kk][np], sBu + (uint32_t)(ci * BST + px) * 2);
                }

            // ---- mma: 2 k-steps of 16 ----
#pragma unroll
            for (int ks = 0; ks < 2; ++ks) {
#pragma unroll
                for (int mt = 0; mt < 2; ++mt) {
                    const uint4 a = afr[mt][ks];
#pragma unroll
                    for (int nt = 0; nt < 8; ++nt)
                        mma16816(d[mt][nt], a.x, a.y, a.z, a.w,
                                 bfr[ks][nt >> 1][(nt & 1) * 2],
                                 bfr[ks][nt >> 1][(nt & 1) * 2 + 1]);
                }
            }
            ++cc;
        }

        // ---- epilogue: gates -> scan update -> htile (fp32) ----
        // thread's d-slots: d[0][nt][q&1 | (q>=2)*2]: gate = mt*2 + (q>>1)
        //   d[0][*][0,1]=i  d[0][*][2,3]=f  d[1][*][0,1]=o  d[1][*][2,3]=cand
#pragma unroll
        for (int nt = 0; nt < 8; ++nt) {
#pragma unroll
            for (int qq = 0; qq < 2; ++qq) {
                int j = nt * 2 + qq;
                float it = sigm(d[0][nt][qq] + bi);
                float ft = sigm(d[0][nt][2 + qq] + bf);
                float ot = sigm(d[1][nt][qq] + bo);
                float cd = d[1][nt][2 + qq] + bc;
                float gd = (cd >= 0.0f) ? (cd + 0.5f) : sigm(cd);
                float inv = 1.0f / (it + ft);
                cst[j] = (ft * inv) * cst[j] + (it * inv) * gd;
                htile[(w * 8 + g4) * HTS + nt * 8 + t4 * 2 + qq] = ot * cst[j];
            }
        }
        __syncthreads();

        // ---- cooperative masked write: htile -> h7 (fp16 x2) or out (fp32) ----
        {
            const int frame = b * S_ + s;
#pragma unroll
            for (int i = 0; i < 16; ++i) {
                int e = tid + i * 128;
                int chr = e >> 6, col = e & 63;
                int pp = p0 + col;
                int rr = pp / 34;
                int cl = pp - rr * 34;
                if ((unsigned)(rr - 1) < 32u && (unsigned)(cl - 1) < 32u) {
                    float hv = htile[chr * HTS + col];
                    if (LAST) {
                        out[((size_t)frame * CL_ + mtile * 32 + chr) * HW_
                            + (rr - 1) * 32 + (cl - 1)] = hv;
                    } else {
                        __half h16 = __float2half_rn(hv);
                        __half* base = (g_h7 + 64)
                            + ((size_t)(frame * CL_ + mtile * 32 + chr)) * NCPY * PLST;
                        base[pp] = h16;               // copy0
                        base[PLST + pp - 1] = h16;    // copy1
                    }
                }
            }
        }

        // ---- reset accumulators for next frame ----
#pragma unroll
        for (int mt = 0; mt < 2; ++mt)
#pragma unroll
            for (int nt = 0; nt < 8; ++nt)
#pragma unroll
                for (int q = 0; q < 4; ++q) d[mt][nt][q] = 0.0f;
    }
}

__global__ void __launch_bounds__(128, 1)
k_fused0(const float* __restrict__ bias) {
    fused_body<1, false>(g_x7 + 64, g_wf0, bias, nullptr);
}

__global__ void __launch_bounds__(128, 1)
k_fused1(const float* __restrict__ bias, float* __restrict__ out) {
    fused_body<2, true>(g_h7 + 64, g_wf1, bias, out);
}

// ---------------- launch ----------------
extern "C" void kernel_launch(void* const* d_in, const int* in_sizes, int n_in,
                              void* d_out, int out_size)
{
    const float* x  = (const float*)d_in[0];
    const float* w0 = (const float*)d_in[1];
    const float* b0 = (const float*)d_in[2];
    const float* w1 = (const float*)d_in[3];
    const float* b1 = (const float*)d_in[4];
    float* out = (float*)d_out;

    k_fill_x7<<<2048, 256>>>(x);
    k_pack_wf<<<512, 256>>>(w0, w1);

    dim3 gg(NT, 2, B_);   // 18 x 2 x 4 = 144 persistent CTAs
    k_fused0<<<gg, 128>>>(b0);
    k_fused1<<<gg, 128>>>(b1, out);
}

// round 16
// speedup vs baseline: 1.9748x; 1.9748x over previous
#include <cuda_runtime.h>
#include <cuda_fp16.h>
#include <cstdint>

// ---------------- problem constants ----------------
#define B_     4
#define S_     16
#define NF     64            // frames = B*S
#define H_     32
#define W_     32
#define HW_    1024
#define CL_    64            // LSTM channels per layer; gate channels = 256
#define GST    1152          // gates scratch stride (18 N-tiles of 64)
#define NT     18            // N tiles per frame
#define PLST   1160          // halves per plane copy
#define NCPY   2             // copies per plane (shift 0 / shift 1)
#define BST    72            // B smem row stride in halves

// ---------------- device scratch (static; no allocations) ----------------
// __device__ globals are zero-initialized at load; halo positions are never
// written by any kernel, so they stay zero (the conv's zero padding).
__device__ __align__(16) __half g_gates[(size_t)NF * 256 * GST];  // fp16 gates
// 2 shifted fp16 padded-plane copies (shift 0 and 1) of x and of h0 (+guards)
__device__ __align__(16) __half g_x7[(size_t)NF * 32 * NCPY * PLST + 64 + 2048];
__device__ __align__(16) __half g_h7[(size_t)NF * 64 * NCPY * PLST + 64 + 2048];
// fragment-ordered fp16 weights (single precision term):
// [chunk][mtile(2)][warp(4)][mt(2)][ks(2)][lane(32)][4 u32]
__device__ __align__(16) uint32_t g_wf0[9  * 4096];
__device__ __align__(16) uint32_t g_wf1[18 * 4096];

// taps in order {-35,-34,-33,-1,0,1,33,34,35}:
// copy q = tap&1; effective (even) offset = tap - q.
__constant__ int c_q[9]   = { 1, 0, 1, 1, 0, 1, 1, 0, 1 };
__constant__ int c_off[9] = { -36, -34, -34, -2, 0, 0, 32, 34, 34 };

// ---------------- helpers ----------------
__device__ __forceinline__ float sigm(float x) { return 1.0f / (1.0f + __expf(-x)); }

__device__ __forceinline__ uint32_t smem_u32(const void* p) {
    uint32_t a;
    asm("{ .reg .u64 t; cvta.to.shared.u64 t, %1; cvt.u32.u64 %0, t; }" : "=r"(a) : "l"(p));
    return a;
}

__device__ __forceinline__ void cp4(uint32_t saddr, const void* gptr) {
    asm volatile("cp.async.ca.shared.global [%0], [%1], 4;"
                 :: "r"(saddr), "l"(gptr) : "memory");
}
__device__ __forceinline__ void cp_commit() {
    asm volatile("cp.async.commit_group;" ::: "memory");
}
__device__ __forceinline__ void cp_wait2() {
    asm volatile("cp.async.wait_group 2;" ::: "memory");
}

__device__ __forceinline__ void ldsm4t(uint32_t r[4], uint32_t addr) {
    asm volatile("ldmatrix.sync.aligned.m8n8.x4.trans.shared.b16 {%0,%1,%2,%3}, [%4];"
        : "=r"(r[0]), "=r"(r[1]), "=r"(r[2]), "=r"(r[3]) : "r"(addr));
}

__device__ __forceinline__ void mma16816(float d[4], uint32_t a0, uint32_t a1,
                                         uint32_t a2, uint32_t a3,
                                         uint32_t b0, uint32_t b1) {
    asm volatile(
        "mma.sync.aligned.m16n8k16.row.col.f32.f16.f16.f32 "
        "{%0,%1,%2,%3}, {%4,%5,%6,%7}, {%8,%9}, {%0,%1,%2,%3};"
        : "+f"(d[0]), "+f"(d[1]), "+f"(d[2]), "+f"(d[3])
        : "r"(a0), "r"(a1), "r"(a2), "r"(a3), "r"(b0), "r"(b1));
}

// ---------------- prologue kernels ----------------
// build the 2 shifted fp16 copies of padded x planes (interior positions only)
__global__ void k_fill_x7(const float* __restrict__ x) {
    __half* xb = g_x7 + 64;
    const int n = NF * 32 * HW_;
    for (int i = blockIdx.x * blockDim.x + threadIdx.x; i < n;
         i += gridDim.x * blockDim.x) {
        int plane = i >> 10, px = i & 1023;
        int r = px >> 5, c = px & 31;
        int p = (r + 1) * 34 + (c + 1);
        __half hv = __float2half_rn(x[i]);
        __half* base = xb + (size_t)plane * NCPY * PLST;
        base[p] = hv;               // copy0 (shift 0)
        base[PLST + p - 1] = hv;    // copy1 (shift 1)
    }
}

// pack weights directly into mma A-fragment order (single fp16 term).
// fragment layout (m16n8k16, row-major A): lane l, reg r:
//   row = (l>>2) + (r&1)*8 ; cols = (l&3)*2 + (r>>1)*8 + {0,1}
__global__ void k_pack_wf(const float* __restrict__ w0, const float* __restrict__ w1) {
    const int n0 = 9 * 4096, n1 = 18 * 4096;
    for (int i = blockIdx.x * blockDim.x + threadIdx.x; i < n0 + n1;
         i += gridDim.x * blockDim.x) {
        bool l1sel = (i >= n0);
        int j = l1sel ? (i - n0) : i;
        int r     = j & 3;
        int lane  = (j >> 2) & 31;
        int ks    = (j >> 7) & 1;
        int mt    = (j >> 8) & 1;
        int w     = (j >> 9) & 3;
        int mtile = (j >> 11) & 1;
        int ch    = j >> 12;
        int row   = mtile * 128 + w * 32 + mt * 16 + (lane >> 2) + (r & 1) * 8;
        int kbase = ks * 16 + (lane & 3) * 2 + (r >> 1) * 8;
        uint32_t outv = 0;
#pragma unroll
        for (int h = 0; h < 2; ++h) {
            int ci = kbase + h;    // 0..31
            float v = l1sel
                ? w1[((size_t)row * 64 + (ch & 1) * 32 + ci) * 9 + (ch >> 1)]
                : w0[((size_t)row * 32 + ci) * 9 + ch];
            outv |= (uint32_t)__half_as_ushort(__float2half_rn(v)) << (16 * h);
        }
        (l1sel ? g_wf1 : g_wf0)[j] = outv;
    }
}

// ---------------- GEMM kernel ----------------
// CTA = 128 threads (4 warps). Tile: M=128 gate channels x N=64 padded pixels,
// one frame. Chunks of 32 ci (K=32, 2 k-steps). A fragments straight from
// fragment-ordered gmem (L2-resident LDG.128); B streamed via 4-byte cp.async
// from the 2 shifted copies, prefetch distance 2, 4-buffer ring.
// Gates written as fp16 (halves traffic; 37.7 MB/layer stays L2-resident).
template <int CPT>   // chunks per tap: 1 (CIN=32) or 2 (CIN=64)
__device__ __forceinline__ void gemm_body(const __half* __restrict__ bpl,
                                          const uint32_t* __restrict__ wf,
                                          __half* __restrict__ gates)
{
    __shared__ __align__(16) __half sBt[4][32 * BST];   // 18.4 KB total

    const int tid  = threadIdx.x, w = tid >> 5, lane = tid & 31;
    const int frame = blockIdx.x / NT, ntile = blockIdx.x - frame * NT;
    const int mtile = blockIdx.y;
    const int p0 = ntile * 64;
    const int NCH = 9 * CPT;
    constexpr int CIN = CPT * 32;

    const int cis = tid >> 3, gs = tid & 7;      // staging coords: 16 ci x 8 chunks

    // async B chunk copy (8 x 4B per thread)
    auto copyB = [&](int ch) {
        const int tap = (CPT == 1) ? ch : (ch >> 1);
        const int ci0 = (CPT == 1) ? 0 : ((ch & 1) * 32);
        const __half* bp = bpl
            + ((size_t)(frame * CIN + ci0) * NCPY + c_q[tap]) * PLST
            + p0 + c_off[tap];
        uint32_t sa = smem_u32(sBt[ch & 3]);
#pragma unroll
        for (int rr = 0; rr < 2; ++rr) {
            int r = cis + rr * 16;
            const __half* src = bp + (size_t)r * (NCPY * PLST) + gs * 8;
            uint32_t dst = sa + (uint32_t)(r * BST + gs * 8) * 2;
#pragma unroll
            for (int jj = 0; jj < 4; ++jj)
                cp4(dst + jj * 4, src + jj * 2);
        }
    };

    float d[2][8][4];
#pragma unroll
    for (int mt = 0; mt < 2; ++mt)
#pragma unroll
        for (int nt = 0; nt < 8; ++nt)
#pragma unroll
            for (int q = 0; q < 4; ++q) d[mt][nt][q] = 0.0f;

    // ---- pipeline prologue: chunks 0,1 in flight ----
    copyB(0); cp_commit();
    copyB(1); cp_commit();

#pragma unroll 1
    for (int ch = 0; ch < NCH; ++ch) {
        // ---- prefetch chunk ch+2 (empty commit keeps group count aligned) ----
        if (ch + 2 < NCH) copyB(ch + 2);
        cp_commit();

        // ---- A fragments for this chunk: 4 independent LDG.128 (L2) ----
        const uint4* af = (const uint4*)wf
                        + ((size_t)(ch * 2 + mtile) * 4 + w) * 128 + lane;
        uint4 afr[2][2];
#pragma unroll
        for (int mt = 0; mt < 2; ++mt)
#pragma unroll
            for (int ks = 0; ks < 2; ++ks)
                afr[mt][ks] = af[(mt * 2 + ks) * 32];

        // ---- wait for chunk ch, make visible ----
        cp_wait2();
        __syncthreads();

        // ---- B fragments via ldmatrix.trans ----
        const uint32_t sBu = smem_u32(sBt[ch & 3]);
        uint32_t bfr[2][4][4];
#pragma unroll
        for (int kk = 0; kk < 2; ++kk)
#pragma unroll
            for (int np = 0; np < 4; ++np) {
                int ci = kk * 16 + ((lane >> 3) & 1) * 8 + (lane & 7);
                int px = np * 16 + (lane >> 4) * 8;
                ldsm4t(bfr[kk][np], sBu + (uint32_t)(ci * BST + px) * 2);
            }

        // ---- mma: 2 k-steps of 16 ----
#pragma unroll
        for (int ks = 0; ks < 2; ++ks) {
#pragma unroll
            for (int mt = 0; mt < 2; ++mt) {
                const uint4 a = afr[mt][ks];
#pragma unroll
                for (int nt = 0; nt < 8; ++nt)
                    mma16816(d[mt][nt], a.x, a.y, a.z, a.w,
                             bfr[ks][nt >> 1][(nt & 1) * 2],
                             bfr[ks][nt >> 1][(nt & 1) * 2 + 1]);
            }
        }
    }

    // ---- epilogue: D -> fp16 gates scratch ----
    const int g4 = lane >> 2, t4 = lane & 3;
#pragma unroll
    for (int mt = 0; mt < 2; ++mt) {
        size_t rowbase = (size_t)frame * 256 + mtile * 128 + w * 32 + mt * 16 + g4;
#pragma unroll
        for (int nt = 0; nt < 8; ++nt) {
            __half* gp = gates + rowbase * GST + p0 + nt * 8 + t4 * 2;
            *(__half2*)gp = __floats2half2_rn(d[mt][nt][0], d[mt][nt][1]);
            *(__half2*)(gp + 8 * (size_t)GST) =
                __floats2half2_rn(d[mt][nt][2], d[mt][nt][3]);
        }
    }
}

__global__ void __launch_bounds__(128, 4)
k_gemm0() { gemm_body<1>(g_x7 + 64, g_wf0, g_gates); }

__global__ void __launch_bounds__(128, 4)
k_gemm1() { gemm_body<2>(g_h7 + 64, g_wf1, g_gates); }

// ---------------- scan kernels ----------------
// thread = (b, lstm-channel, interior pixel); loops s, cell state in register.
// Software-pipelined: frame s+1's gates loaded while computing frame s.
// PADOUT=true writes the 2 shifted fp16 plane copies for the next GEMM.
template <bool PADOUT>
__global__ void __launch_bounds__(256)
k_scan(const float* __restrict__ bias, float* __restrict__ out)
{
    int gtid = blockIdx.x * blockDim.x + threadIdx.x;  // 0 .. 262143
    int px = gtid & 1023;
    int ch = (gtid >> 10) & 63;
    int b  = gtid >> 16;
    int r = px >> 5, c = px & 31;
    int p = (r + 1) * 34 + (c + 1);

    float bi = __ldg(bias + ch);
    float bf = __ldg(bias + 64 + ch);
    float bo = __ldg(bias + 128 + ch);
    float bc = __ldg(bias + 192 + ch);

    float cst = 0.5f;
    __half* h7 = g_h7 + 64;

    const __half* gg0 = g_gates + (size_t)(b * S_) * 256 * GST
                      + (size_t)ch * GST + p;
    const size_t fstep = (size_t)256 * GST;

    float vi = __half2float(gg0[0]);
    float vf = __half2float(gg0[64 * (size_t)GST]);
    float vo = __half2float(gg0[128 * (size_t)GST]);
    float vc = __half2float(gg0[192 * (size_t)GST]);

#pragma unroll 1
    for (int s = 0; s < S_; ++s) {
        float ni = 0.f, nf = 0.f, no = 0.f, nc = 0.f;
        if (s + 1 < S_) {
            const __half* gn = gg0 + (size_t)(s + 1) * fstep;
            ni = __half2float(gn[0]);
            nf = __half2float(gn[64 * (size_t)GST]);
            no = __half2float(gn[128 * (size_t)GST]);
            nc = __half2float(gn[192 * (size_t)GST]);
        }
        float it = sigm(vi + bi);
        float ft = sigm(vf + bf);
        float ot = sigm(vo + bo);
        float cd = vc + bc;
        float gd = (cd >= 0.0f) ? (cd + 0.5f) : sigm(cd);
        float inv = 1.0f / (it + ft);
        cst = (ft * inv) * cst + (it * inv) * gd;
        float hv = ot * cst;
        int frame = b * S_ + s;
        if (PADOUT) {
            __half h16 = __float2half_rn(hv);
            __half* base = h7 + ((size_t)frame * CL_ + ch) * NCPY * PLST;
            base[p] = h16;               // copy0 (shift 0)
            base[PLST + p - 1] = h16;    // copy1 (shift 1)
        } else {
            out[((size_t)frame * CL_ + ch) * HW_ + px] = hv;
        }
        vi = ni; vf = nf; vo = no; vc = nc;
    }
}

// ---------------- launch ----------------
extern "C" void kernel_launch(void* const* d_in, const int* in_sizes, int n_in,
                              void* d_out, int out_size)
{
    const float* x  = (const float*)d_in[0];
    const float* w0 = (const float*)d_in[1];
    const float* b0 = (const float*)d_in[2];
    const float* w1 = (const float*)d_in[3];
    const float* b1 = (const float*)d_in[4];
    float* out = (float*)d_out;

    k_fill_x7<<<2048, 256>>>(x);
    k_pack_wf<<<512, 256>>>(w0, w1);

    dim3 gg(NF * NT, 2, 1);   // 1152 x 2 CTAs
    k_gemm0<<<gg, 128>>>();
    k_scan<true><<<1024, 256>>>(b0, nullptr);
    k_gemm1<<<gg, 128>>>();
    k_scan<false><<<1024, 256>>>(b1, out);
}

// round 17
// speedup vs baseline: 2.0956x; 1.0612x over previous
#include <cuda_runtime.h>
#include <cuda_fp16.h>
#include <cstdint>

// ---------------- problem constants ----------------
#define B_     4
#define S_     16
#define NF     64            // frames = B*S
#define H_     32
#define W_     32
#define HW_    1024
#define CL_    64            // LSTM channels per layer; gate channels = 256
#define GST    1152          // gates scratch stride (18 N-tiles of 64)
#define NT     18            // N tiles per frame
#define PLST   1160          // halves per plane copy
#define NCPY   2             // copies per plane (shift 0 / shift 1)
#define BST    72            // B smem row stride in halves

// ---------------- device scratch (static; no allocations) ----------------
// __device__ globals are zero-initialized at load; halo positions are never
// written by any kernel, so they stay zero (the conv's zero padding).
__device__ __align__(16) __half g_gates[(size_t)NF * 256 * GST];  // fp16 gates
// 2 shifted fp16 padded-plane copies (shift 0 and 1) of x and of h0 (+guards)
__device__ __align__(16) __half g_x7[(size_t)NF * 32 * NCPY * PLST + 64 + 2048];
__device__ __align__(16) __half g_h7[(size_t)NF * 64 * NCPY * PLST + 64 + 2048];
// fragment-ordered fp16 weights (single precision term):
// [chunk][mtile(2)][warp(4)][mt(2)][ks(2)][lane(32)][4 u32]
__device__ __align__(16) uint32_t g_wf0[9  * 4096];
__device__ __align__(16) uint32_t g_wf1[18 * 4096];

// taps in order {-35,-34,-33,-1,0,1,33,34,35}:
// copy q = tap&1; effective (even) offset = tap - q.
__constant__ int c_q[9]   = { 1, 0, 1, 1, 0, 1, 1, 0, 1 };
__constant__ int c_off[9] = { -36, -34, -34, -2, 0, 0, 32, 34, 34 };

// ---------------- helpers ----------------
__device__ __forceinline__ float sigm(float x) { return 1.0f / (1.0f + __expf(-x)); }

__device__ __forceinline__ uint32_t smem_u32(const void* p) {
    uint32_t a;
    asm("{ .reg .u64 t; cvta.to.shared.u64 t, %1; cvt.u32.u64 %0, t; }" : "=r"(a) : "l"(p));
    return a;
}

__device__ __forceinline__ void cp4(uint32_t saddr, const void* gptr) {
    asm volatile("cp.async.ca.shared.global [%0], [%1], 4;"
                 :: "r"(saddr), "l"(gptr) : "memory");
}
__device__ __forceinline__ void cp_commit() {
    asm volatile("cp.async.commit_group;" ::: "memory");
}
__device__ __forceinline__ void cp_wait2() {
    asm volatile("cp.async.wait_group 2;" ::: "memory");
}

__device__ __forceinline__ void ldsm4t(uint32_t r[4], uint32_t addr) {
    asm volatile("ldmatrix.sync.aligned.m8n8.x4.trans.shared.b16 {%0,%1,%2,%3}, [%4];"
        : "=r"(r[0]), "=r"(r[1]), "=r"(r[2]), "=r"(r[3]) : "r"(addr));
}

__device__ __forceinline__ void mma16816(float d[4], uint32_t a0, uint32_t a1,
                                         uint32_t a2, uint32_t a3,
                                         uint32_t b0, uint32_t b1) {
    asm volatile(
        "mma.sync.aligned.m16n8k16.row.col.f32.f16.f16.f32 "
        "{%0,%1,%2,%3}, {%4,%5,%6,%7}, {%8,%9}, {%0,%1,%2,%3};"
        : "+f"(d[0]), "+f"(d[1]), "+f"(d[2]), "+f"(d[3])
        : "r"(a0), "r"(a1), "r"(a2), "r"(a3), "r"(b0), "r"(b1));
}

// ---------------- prologue kernels ----------------
// build the 2 shifted fp16 copies of padded x planes (interior positions only)
__global__ void k_fill_x7(const float* __restrict__ x) {
    __half* xb = g_x7 + 64;
    const int n = NF * 32 * HW_;
    for (int i = blockIdx.x * blockDim.x + threadIdx.x; i < n;
         i += gridDim.x * blockDim.x) {
        int plane = i >> 10, px = i & 1023;
        int r = px >> 5, c = px & 31;
        int p = (r + 1) * 34 + (c + 1);
        __half hv = __float2half_rn(x[i]);
        __half* base = xb + (size_t)plane * NCPY * PLST;
        base[p] = hv;               // copy0 (shift 0)
        base[PLST + p - 1] = hv;    // copy1 (shift 1)
    }
}

// pack weights directly into mma A-fragment order (single fp16 term).
// fragment layout (m16n8k16, row-major A): lane l, reg r:
//   row = (l>>2) + (r&1)*8 ; cols = (l&3)*2 + (r>>1)*8 + {0,1}
__global__ void k_pack_wf(const float* __restrict__ w0, const float* __restrict__ w1) {
    const int n0 = 9 * 4096, n1 = 18 * 4096;
    for (int i = blockIdx.x * blockDim.x + threadIdx.x; i < n0 + n1;
         i += gridDim.x * blockDim.x) {
        bool l1sel = (i >= n0);
        int j = l1sel ? (i - n0) : i;
        int r     = j & 3;
        int lane  = (j >> 2) & 31;
        int ks    = (j >> 7) & 1;
        int mt    = (j >> 8) & 1;
        int w     = (j >> 9) & 3;
        int mtile = (j >> 11) & 1;
        int ch    = j >> 12;
        int row   = mtile * 128 + w * 32 + mt * 16 + (lane >> 2) + (r & 1) * 8;
        int kbase = ks * 16 + (lane & 3) * 2 + (r >> 1) * 8;
        uint32_t outv = 0;
#pragma unroll
        for (int h = 0; h < 2; ++h) {
            int ci = kbase + h;    // 0..31
            float v = l1sel
                ? w1[((size_t)row * 64 + (ch & 1) * 32 + ci) * 9 + (ch >> 1)]
                : w0[((size_t)row * 32 + ci) * 9 + ch];
            outv |= (uint32_t)__half_as_ushort(__float2half_rn(v)) << (16 * h);
        }
        (l1sel ? g_wf1 : g_wf0)[j] = outv;
    }
}

// ---------------- GEMM kernel ----------------
// CTA = 256 threads (8 warps): full M=256 gate channels x N=64 padded pixels,
// one frame. Warps 0-3 -> mtile 0, warps 4-7 -> mtile 1; both share one staged
// B tile (halves B global traffic vs split CTAs). Chunks of 32 ci; A fragments
// straight from fragment-ordered gmem; B via 4-byte cp.async, distance 2,
// 4-buffer ring. Gates written fp16.
template <int CPT>   // chunks per tap: 1 (CIN=32) or 2 (CIN=64)
__device__ __forceinline__ void gemm_body(const __half* __restrict__ bpl,
                                          const uint32_t* __restrict__ wf,
                                          __half* __restrict__ gates)
{
    __shared__ __align__(16) __half sBt[4][32 * BST];   // 18.4 KB total

    const int tid  = threadIdx.x, w = tid >> 5, lane = tid & 31;
    const int mtile = w >> 2, wl = w & 3;
    const int frame = blockIdx.x / NT, ntile = blockIdx.x - frame * NT;
    const int p0 = ntile * 64;
    const int NCH = 9 * CPT;
    constexpr int CIN = CPT * 32;

    const int cis = tid >> 3, gs = tid & 7;   // staging: 32 ci x 8 px-chunks

    // async B chunk copy (4 x 4B per thread, 256 threads cover 32x64 tile)
    auto copyB = [&](int ch) {
        const int tap = (CPT == 1) ? ch : (ch >> 1);
        const int ci0 = (CPT == 1) ? 0 : ((ch & 1) * 32);
        const __half* bp = bpl
            + ((size_t)(frame * CIN + ci0) * NCPY + c_q[tap]) * PLST
            + p0 + c_off[tap];
        const __half* src = bp + (size_t)cis * (NCPY * PLST) + gs * 8;
        uint32_t dst = smem_u32(sBt[ch & 3]) + (uint32_t)(cis * BST + gs * 8) * 2;
#pragma unroll
        for (int jj = 0; jj < 4; ++jj)
            cp4(dst + jj * 4, src + jj * 2);
    };

    float d[2][8][4];
#pragma unroll
    for (int mt = 0; mt < 2; ++mt)
#pragma unroll
        for (int nt = 0; nt < 8; ++nt)
#pragma unroll
            for (int q = 0; q < 4; ++q) d[mt][nt][q] = 0.0f;

    // ---- pipeline prologue: chunks 0,1 in flight ----
    copyB(0); cp_commit();
    copyB(1); cp_commit();

#pragma unroll 1
    for (int ch = 0; ch < NCH; ++ch) {
        // ---- prefetch chunk ch+2 (empty commit keeps group count aligned) ----
        if (ch + 2 < NCH) copyB(ch + 2);
        cp_commit();

        // ---- A fragments for this chunk: 4 independent LDG.128 (L2) ----
        const uint4* af = (const uint4*)wf
                        + ((size_t)(ch * 2 + mtile) * 4 + wl) * 128 + lane;
        uint4 afr[2][2];
#pragma unroll
        for (int mt = 0; mt < 2; ++mt)
#pragma unroll
            for (int ks = 0; ks < 2; ++ks)
                afr[mt][ks] = af[(mt * 2 + ks) * 32];

        // ---- wait for chunk ch, make visible ----
        cp_wait2();
        __syncthreads();

        // ---- B fragments via ldmatrix.trans ----
        const uint32_t sBu = smem_u32(sBt[ch & 3]);
        uint32_t bfr[2][4][4];
#pragma unroll
        for (int kk = 0; kk < 2; ++kk)
#pragma unroll
            for (int np = 0; np < 4; ++np) {
                int ci = kk * 16 + ((lane >> 3) & 1) * 8 + (lane & 7);
                int px = np * 16 + (lane >> 4) * 8;
                ldsm4t(bfr[kk][np], sBu + (uint32_t)(ci * BST + px) * 2);
            }

        // ---- mma: 2 k-steps of 16 ----
#pragma unroll
        for (int ks = 0; ks < 2; ++ks) {
#pragma unroll
            for (int mt = 0; mt < 2; ++mt) {
                const uint4 a = afr[mt][ks];
#pragma unroll
                for (int nt = 0; nt < 8; ++nt)
                    mma16816(d[mt][nt], a.x, a.y, a.z, a.w,
                             bfr[ks][nt >> 1][(nt & 1) * 2],
                             bfr[ks][nt >> 1][(nt & 1) * 2 + 1]);
            }
        }
    }

    // ---- epilogue: D -> fp16 gates scratch ----
    const int g4 = lane >> 2, t4 = lane & 3;
#pragma unroll
    for (int mt = 0; mt < 2; ++mt) {
        size_t rowbase = (size_t)frame * 256 + mtile * 128 + wl * 32 + mt * 16 + g4;
#pragma unroll
        for (int nt = 0; nt < 8; ++nt) {
            __half* gp = gates + rowbase * GST + p0 + nt * 8 + t4 * 2;
            *(__half2*)gp = __floats2half2_rn(d[mt][nt][0], d[mt][nt][1]);
            *(__half2*)(gp + 8 * (size_t)GST) =
                __floats2half2_rn(d[mt][nt][2], d[mt][nt][3]);
        }
    }
}

__global__ void __launch_bounds__(256, 2)
k_gemm0() { gemm_body<1>(g_x7 + 64, g_wf0, g_gates); }

__global__ void __launch_bounds__(256, 2)
k_gemm1() { gemm_body<2>(g_h7 + 64, g_wf1, g_gates); }

// ---------------- scan kernels ----------------
// thread = (b, lstm-channel, PAIR of padded positions pp=2t, pp+1); loops s
// with 2 cell states in registers; half2 gate loads (4 per frame per pair).
// PADOUT=true writes the 2 shifted fp16 plane copies for the next GEMM.
template <bool PADOUT>
__global__ void __launch_bounds__(256)
k_scan(const float* __restrict__ bias, float* __restrict__ out)
{
    int gtid = blockIdx.x * blockDim.x + threadIdx.x;  // 0 .. 147455
    int t  = gtid % 576;                // position-pair index
    int rc = gtid / 576;
    int ch = rc & 63;
    int b  = rc >> 6;
    int pp = 2 * t;                     // padded positions pp, pp+1 (pp even)

    // validity + output coords per lane
    int rr0 = pp / 34,        cl0 = pp - rr0 * 34;
    int rr1 = (pp + 1) / 34,  cl1 = (pp + 1) - rr1 * 34;
    bool v0 = ((unsigned)(rr0 - 1) < 32u) && ((unsigned)(cl0 - 1) < 32u);
    bool v1 = ((unsigned)(rr1 - 1) < 32u) && ((unsigned)(cl1 - 1) < 32u);
    int px0 = (rr0 - 1) * 32 + (cl0 - 1);
    int px1 = (rr1 - 1) * 32 + (cl1 - 1);

    float bi = __ldg(bias + ch);
    float bf = __ldg(bias + 64 + ch);
    float bo = __ldg(bias + 128 + ch);
    float bc = __ldg(bias + 192 + ch);

    float c0 = 0.5f, c1 = 0.5f;
    __half* h7 = g_h7 + 64;

    const __half* gg0 = g_gates + (size_t)(b * S_) * 256 * GST
                      + (size_t)ch * GST + pp;
    const size_t fstep = (size_t)256 * GST;

    __half2 vi = *(const __half2*)(gg0);
    __half2 vf = *(const __half2*)(gg0 + 64 * (size_t)GST);
    __half2 vo = *(const __half2*)(gg0 + 128 * (size_t)GST);
    __half2 vc = *(const __half2*)(gg0 + 192 * (size_t)GST);

#pragma unroll 1
    for (int s = 0; s < S_; ++s) {
        __half2 ni = __half2(), nf = __half2(), no = __half2(), nc = __half2();
        if (s + 1 < S_) {
            const __half* gn = gg0 + (size_t)(s + 1) * fstep;
            ni = *(const __half2*)(gn);
            nf = *(const __half2*)(gn + 64 * (size_t)GST);
            no = *(const __half2*)(gn + 128 * (size_t)GST);
            nc = *(const __half2*)(gn + 192 * (size_t)GST);
        }
        float2 fi = __half22float2(vi), ff = __half22float2(vf);
        float2 fo = __half22float2(vo), fc = __half22float2(vc);

        float it0 = sigm(fi.x + bi), it1 = sigm(fi.y + bi);
        float ft0 = sigm(ff.x + bf), ft1 = sigm(ff.y + bf);
        float ot0 = sigm(fo.x + bo), ot1 = sigm(fo.y + bo);
        float cd0 = fc.x + bc,       cd1 = fc.y + bc;
        float gd0 = (cd0 >= 0.0f) ? (cd0 + 0.5f) : sigm(cd0);
        float gd1 = (cd1 >= 0.0f) ? (cd1 + 0.5f) : sigm(cd1);
        float in0 = 1.0f / (it0 + ft0), in1 = 1.0f / (it1 + ft1);
        c0 = (ft0 * in0) * c0 + (it0 * in0) * gd0;
        c1 = (ft1 * in1) * c1 + (it1 * in1) * gd1;
        float h0 = ot0 * c0, h1 = ot1 * c1;

        int frame = b * S_ + s;
        if (PADOUT) {
            __half q0 = __float2half_rn(h0), q1 = __float2half_rn(h1);
            __half* base = h7 + ((size_t)frame * CL_ + ch) * NCPY * PLST;
            // copy0 (shift 0): positions pp, pp+1 — only valid ones carry data,
            // but writing g(0-pad)=garbage? No: invalid positions must stay 0.
            if (v0) { base[pp] = q0;      base[PLST + pp - 1] = q0; }
            if (v1) { base[pp + 1] = q1;  base[PLST + pp] = q1; }
            if (v0 && out) {}
        } else {
            if (v0) out[((size_t)frame * CL_ + ch) * HW_ + px0] = h0;
            if (v1) out[((size_t)frame * CL_ + ch) * HW_ + px1] = h1;
        }
        vi = ni; vf = nf; vo = no; vc = nc;
    }
}

// ---------------- launch ----------------
extern "C" void kernel_launch(void* const* d_in, const int* in_sizes, int n_in,
                              void* d_out, int out_size)
{
    const float* x  = (const float*)d_in[0];
    const float* w0 = (const float*)d_in[1];
    const float* b0 = (const float*)d_in[2];
    const float* w1 = (const float*)d_in[3];
    const float* b1 = (const float*)d_in[4];
    float* out = (float*)d_out;

    k_fill_x7<<<2048, 256>>>(x);
    k_pack_wf<<<512, 256>>>(w0, w1);

    dim3 gg(NF * NT, 1, 1);   // 1152 merged CTAs (256 threads)
    k_gemm0<<<gg, 256>>>();
    k_scan<true><<<576, 256>>>(b0, nullptr);
    k_gemm1<<<gg, 256>>>();
    k_scan<false><<<576, 256>>>(b1, out);
}